// round 8
// baseline (speedup 1.0000x reference)
#include <cuda_runtime.h>
#include <math.h>

// ---------------------------------------------------------------------------
// YoloV1Loss — R8: R6-K1 (best main pass, ~43us) fused with last-block
// finalize using RELEASE-only ordering per block:
//   * 3135 blocks: __syncthreads -> atom.release.gpu.add (no L1 flush)
//   * last block only: fence.acq_rel.gpu (one IVALL), then scan 3136 meta
//     records, gated sum, boundary partial, write scalar.
// Kills the ~11.4us grid=1 second-kernel launch floor (R5/R6 evidence) while
// avoiding R3's per-block fence.sc disaster (IVALL x3136 = +17us).
// ---------------------------------------------------------------------------

#define TPB   256
#define RPT   256
#define MAXT  4096
#define NCLS  20

__device__ float4   g_meta[MAXT];            // (csum, noobj, count, 0)
__device__ float    g_contrib[MAXT * RPT];   // rank-compacted per tile
__device__ unsigned g_done;                  // zero-init; finalizer resets

__global__ void __launch_bounds__(TPB)
yolo_fused(const float* __restrict__ p, const float* __restrict__ t,
           float* __restrict__ out, int nrows) {
    extern __shared__ float smem[];
    float* ps  = smem;                 // TPB*30 floats
    float* tsd = smem + TPB * 30;      // TPB*30 floats
    __shared__ int      wtot[TPB / 32];
    __shared__ float    wredN[TPB / 32];
    __shared__ float    wredC[TPB / 32];
    __shared__ double   sd[TPB / 32];
    __shared__ int      s_bb, s_take;
    __shared__ unsigned s_rank;

    const int tid  = threadIdx.x;
    const int bid  = blockIdx.x;
    const int row0 = bid * RPT;
    const int lane = tid & 31;
    const int wid  = tid >> 5;
    const int rows = min(RPT, nrows - row0);
    const int n4   = (rows * 30) >> 2;
    const size_t base = (size_t)row0 * 30;

    // ---- full-row contiguous staging: pure float4 stream ----
    {
        const float4* pg = (const float4*)(p + base);
        const float4* tg = (const float4*)(t + base);
        float4* p4 = (float4*)ps;
        float4* t4 = (float4*)tsd;
        for (int i = tid; i < n4; i += TPB) {
            p4[i] = pg[i];
            t4[i] = tg[i];
        }
        for (int i = (n4 << 2) + tid; i < rows * 30; i += TPB) {  // odd tail
            ps[i]  = p[base + i];
            tsd[i] = t[base + i];
        }
    }
    __syncthreads();

    const bool inrange = (tid < rows);
    const float* pr = ps  + tid * 30;
    const float* tr = tsd + tid * 30;

    const float conf = inrange ? tr[4] : -1.0f;
    const bool  cm   = (conf == 1.0f);

    // in-block inclusive rank of coord rows
    const unsigned bal = __ballot_sync(0xffffffffu, cm);
    unsigned le_mask;
    asm("mov.u32 %0, %%lanemask_le;" : "=r"(le_mask));
    const int inc = __popc(bal & le_mask);
    if (lane == 31) wtot[wid] = __popc(bal);
    __syncthreads();
    int woff = 0, ctot = 0;
#pragma unroll
    for (int i = 0; i < TPB / 32; i++) {
        const int c = wtot[i];
        if (i < wid) woff += c;
        ctot += c;
    }

    // noobj term
    float nv = 0.0f;
    if (inrange && conf == 0.0f) {
        const float d0 = pr[4] - tr[4];
        const float d1 = pr[9] - tr[9];
        nv = 0.5f * (d0 * d0 + d1 * d1);
    }

    // coord term (global gate resolved by finalizer)
    float cv = 0.0f;
    if (cm) {
        const float C = 1.0f / 7.0f;
        const float tb0 = tr[0] * tr[0], tb1 = tr[1] * tr[1];
        const float tb2 = tr[2] * tr[2], tb3 = tr[3] * tr[3];
        const float tax = tb0 * C - tb2, tay = tb1 * C - tb3;
        const float tbx = tax * C + tb2, tby = tay * C + tb3;
        const float at2 = (tbx - tax) * (tby - tay);

        float iou0 = 0.0f, iou1 = 0.0f;
#pragma unroll
        for (int b = 0; b < 2; b++) {
            const float x = pr[b * 5 + 0], y = pr[b * 5 + 1];
            const float w = pr[b * 5 + 2], h = pr[b * 5 + 3];
            const float ax = x * C - w,  ay = y * C - h;
            const float bx = ax * C + w, by = ay * C + h;
            const float iw = fmaxf(fminf(bx, tbx) - fmaxf(ax, tax), 0.0f);
            const float ih = fmaxf(fminf(by, tby) - fmaxf(ay, tay), 0.0f);
            const float inter = iw * ih;
            const float ap2 = (bx - ax) * (by - ay);
            const float iou = inter / (ap2 + at2 - inter);
            if (b == 0) iou0 = iou; else iou1 = iou;
        }
        int idx;
        if (isnan(iou0))      idx = 0;   // numpy argmax: NaN wins, first occ.
        else if (isnan(iou1)) idx = 1;
        else                  idx = (iou1 > iou0) ? 1 : 0;

        const int ob = idx * 5;
        const float s0 = pr[ob + 0] - tr[0];
        const float s1 = pr[ob + 1] - tr[1];
        const float s2 = pr[ob + 2] - tr[2];
        const float s3 = pr[ob + 3] - tr[3];

        // class argmax from smem (first strict max) + paired p-select
        float best = tr[10];
        float clp  = pr[10];
#pragma unroll
        for (int j = 1; j < NCLS; j++) {
            const float v = tr[10 + j];
            const bool  u = (v > best);
            best = u ? v : best;
            clp  = u ? pr[10 + j] : clp;
        }
        const float clv = clp - 1.0f;

        cv = 5.0f * (s0 * s0 + s1 * s1 + s2 * s2 + s3 * s3 + 2.0f * clv * clv);
        g_contrib[bid * RPT + (woff + inc - 1)] = cv;
    }

    // block reductions: noobj + coord sums
#pragma unroll
    for (int o = 16; o > 0; o >>= 1) {
        nv += __shfl_down_sync(0xffffffffu, nv, o);
        cv += __shfl_down_sync(0xffffffffu, cv, o);
    }
    if (lane == 0) { wredN[wid] = nv; wredC[wid] = cv; }
    __syncthreads();
    if (tid == 0) {
        float sn = 0.0f, sc = 0.0f;
#pragma unroll
        for (int i = 0; i < TPB / 32; i++) { sn += wredN[i]; sc += wredC[i]; }
        g_meta[bid] = make_float4(sc, sn, __int_as_float(ctot), 0.0f);
    }

    // =============== last-block finalize (release-only publish) ===============
    __syncthreads();   // all block writes happen-before tid0's release atomic
    if (tid == 0) {
        unsigned old;
        asm volatile("atom.release.gpu.add.u32 %0, [%1], 1;"
                     : "=r"(old) : "l"(&g_done) : "memory");
        s_rank = old;
    }
    __syncthreads();
    if (s_rank != (unsigned)(gridDim.x - 1)) return;

    // acquire everyone's writes (single block pays the L1 invalidate)
    asm volatile("fence.acq_rel.gpu;" ::: "memory");
    __syncthreads();

    const int nt = gridDim.x;
    const int CH = (nt + TPB - 1) / TPB;
    const int i0 = tid * CH;

    if (tid == 0) { s_bb = -1; s_take = 0; }

    // pass 1: per-thread chunk count sum
    int lsum = 0;
    for (int k = 0; k < CH; k++) {
        const int i = i0 + k;
        if (i < nt) lsum += __float_as_int(g_meta[i].z);
    }
    int incs = lsum;
#pragma unroll
    for (int o = 1; o < 32; o <<= 1) {
        const int x = __shfl_up_sync(0xffffffffu, incs, o);
        if (lane >= o) incs += x;
    }
    const int ex = incs - lsum;
    if (lane == 31) wtot[wid] = incs;
    __syncthreads();
    int wbase = 0, total = 0;
#pragma unroll
    for (int i = 0; i < TPB / 32; i++) {
        const int c = wtot[i];
        if (i < wid) wbase += c;
        total += c;
    }
    const int half = total >> 1;                 // n_obj // 2

    // pass 2: gated sum; locate single boundary tile
    double acc = 0.0;
    int P = wbase + ex;
    for (int k = 0; k < CH; k++) {
        const int i = i0 + k;
        if (i < nt) {
            const float4 m   = g_meta[i];
            const int    cnt = __float_as_int(m.z);
            const int   take = min(cnt, max(0, half - P));
            if (take == cnt)    acc += (double)m.x;
            else if (take > 0) { s_bb = i; s_take = take; }
            acc += (double)m.y;
            P += cnt;
        }
    }
    __syncthreads();

    if (s_bb >= 0) {                              // <=256-float partial
        const float* cb = g_contrib + s_bb * RPT;
        for (int i = tid; i < s_take; i += TPB) acc += (double)cb[i];
    }

#pragma unroll
    for (int o = 16; o > 0; o >>= 1)
        acc += __shfl_down_sync(0xffffffffu, acc, o);
    if (lane == 0) sd[wid] = acc;
    __syncthreads();
    if (tid == 0) {
        double s = 0.0;
#pragma unroll
        for (int i = 0; i < TPB / 32; i++) s += sd[i];
        out[0] = (float)s;
        g_done = 0u;                              // reset for next replay
    }
}

// ---------------------------------------------------------------------------
extern "C" void kernel_launch(void* const* d_in, const int* in_sizes, int n_in,
                              void* d_out, int out_size) {
    const float* p = (const float*)d_in[0];
    const float* t = (const float*)d_in[1];

    const int nrows = in_sizes[0] / 30;
    const int nt    = (nrows + RPT - 1) / RPT;

    const int smem_bytes = 2 * TPB * 30 * (int)sizeof(float);   // 61440
    cudaFuncSetAttribute(yolo_fused,
                         cudaFuncAttributeMaxDynamicSharedMemorySize,
                         smem_bytes);

    yolo_fused<<<nt, TPB, smem_bytes>>>(p, t, (float*)d_out, nrows);
}